// round 1
// baseline (speedup 1.0000x reference)
#include <cuda_runtime.h>

// ModifiedLogicSegLoss: loss = sum_{b,c} w[c] * (softplus(x) - t*x)
//   w[c] = sum_l La[l,c]*lam[l] / 128   (levels partition classes; clamp never fires)
// B=262144, C=128 -> 2^23 float4 vectors per input array.

#define NBLOCKS   1024
#define NTHREADS  256
#define NC        128
#define NVEC      (1u << 23)                       // 8,388,608 float4 elements
#define ITERS     (NVEC / (NBLOCKS * NTHREADS))    // 32, compile-time

__device__ float g_partials[NBLOCKS];

__device__ __forceinline__ float bce_elem(float x, float t) {
    // softplus(x) - t*x, stable form: max(x,0) + log1p(exp(-|x|))
    float e  = __expf(-fabsf(x));
    float sp = fmaxf(x, 0.0f) + __logf(1.0f + e);
    return fmaf(-t, x, sp);
}

__global__ void __launch_bounds__(NTHREADS)
loss_main(const float4* __restrict__ yp, const float4* __restrict__ yt,
          const float*  __restrict__ La, const float*  __restrict__ lam) {
    __shared__ __align__(16) float w[NC];
    __shared__ float wred[NTHREADS / 32];
    const int tid = threadIdx.x;

    // Build per-class weights once per block (La: [4,128], lam: [4])
    if (tid < NC) {
        float a = 0.0f;
        #pragma unroll
        for (int l = 0; l < 4; ++l)
            a = fmaf(La[l * NC + tid], lam[l], a);
        w[tid] = a * (1.0f / (float)NC);
    }
    __syncthreads();

    const unsigned gid = blockIdx.x * NTHREADS + tid;
    // Grid stride (2^18) is a multiple of 32 -> class-quad index is loop-invariant.
    const float4 wv = reinterpret_cast<const float4*>(w)[gid & 31];

    float acc = 0.0f;
    #pragma unroll 4
    for (int i = 0; i < ITERS; ++i) {
        const unsigned v = gid + (unsigned)i * (NBLOCKS * NTHREADS);
        const float4 x = yp[v];
        const float4 t = yt[v];
        float s =      wv.x * bce_elem(x.x, t.x);
        s = fmaf(wv.y, bce_elem(x.y, t.y), s);
        s = fmaf(wv.z, bce_elem(x.z, t.z), s);
        s = fmaf(wv.w, bce_elem(x.w, t.w), s);
        acc += s;
    }

    // Warp reduce
    #pragma unroll
    for (int o = 16; o > 0; o >>= 1)
        acc += __shfl_xor_sync(0xffffffffu, acc, o);
    if ((tid & 31) == 0) wred[tid >> 5] = acc;
    __syncthreads();

    if (tid < NTHREADS / 32) {               // 8 threads
        float a = wred[tid];
        #pragma unroll
        for (int o = NTHREADS / 64; o > 0; o >>= 1)
            a += __shfl_xor_sync(0xffu, a, o);
        if (tid == 0) g_partials[blockIdx.x] = a;
    }
}

__global__ void loss_reduce(float* __restrict__ out) {
    __shared__ float s[256];
    const int tid = threadIdx.x;
    float a = 0.0f;
    for (int i = tid; i < NBLOCKS; i += 256)   // fixed order -> deterministic
        a += g_partials[i];
    s[tid] = a;
    __syncthreads();
    #pragma unroll
    for (int o = 128; o > 0; o >>= 1) {
        if (tid < o) s[tid] += s[tid + o];
        __syncthreads();
    }
    if (tid == 0) out[0] = s[0];
}

extern "C" void kernel_launch(void* const* d_in, const int* in_sizes, int n_in,
                              void* d_out, int out_size) {
    (void)in_sizes; (void)n_in; (void)out_size;
    loss_main<<<NBLOCKS, NTHREADS>>>(
        (const float4*)d_in[0], (const float4*)d_in[1],
        (const float*)d_in[2],  (const float*)d_in[3]);
    loss_reduce<<<1, 256>>>((float*)d_out);
}

// round 2
// speedup vs baseline: 1.0095x; 1.0095x over previous
#include <cuda_runtime.h>

// ModifiedLogicSegLoss: loss = sum_{b,c} w[c] * (softplus(x) - t*x)
//   w[c] = sum_l La[l,c]*lam[l] / 128   (levels partition classes; clamp never fires)
// B=262144, C=128 -> 2^23 float4 vectors per input array.
// Single fused kernel: last block to finish does the deterministic final reduce.

#define NBLOCKS   1024
#define NTHREADS  256
#define NC        128
#define NVEC      (1u << 23)                       // 8,388,608 float4 elements
#define ITERS     (NVEC / (NBLOCKS * NTHREADS))    // 32, compile-time

__device__ float g_partials[NBLOCKS];
__device__ unsigned int g_done = 0;                // reset by last block each launch

__device__ __forceinline__ float bce_elem(float x, float t) {
    // softplus(x) - t*x, stable form: max(x,0) + log1p(exp(-|x|))
    float e  = __expf(-fabsf(x));
    float sp = fmaxf(x, 0.0f) + __logf(1.0f + e);
    return fmaf(-t, x, sp);
}

__global__ void __launch_bounds__(NTHREADS)
loss_fused(const float4* __restrict__ yp, const float4* __restrict__ yt,
           const float*  __restrict__ La, const float*  __restrict__ lam,
           float* __restrict__ out) {
    __shared__ __align__(16) float w[NC];
    __shared__ float wred[NTHREADS / 32];
    __shared__ bool s_last;
    const int tid = threadIdx.x;

    // Build per-class weights once per block (La: [4,128], lam: [4])
    if (tid < NC) {
        float a = 0.0f;
        #pragma unroll
        for (int l = 0; l < 4; ++l)
            a = fmaf(La[l * NC + tid], lam[l], a);
        w[tid] = a * (1.0f / (float)NC);
    }
    __syncthreads();

    const unsigned gid = blockIdx.x * NTHREADS + tid;
    // Grid stride (2^18) is a multiple of 32 -> class-quad index is loop-invariant.
    const float4 wv = reinterpret_cast<const float4*>(w)[gid & 31];

    float acc = 0.0f;
    #pragma unroll 8
    for (int i = 0; i < ITERS; ++i) {
        const unsigned v = gid + (unsigned)i * (NBLOCKS * NTHREADS);
        const float4 x = yp[v];
        const float4 t = yt[v];
        float s =      wv.x * bce_elem(x.x, t.x);
        s = fmaf(wv.y, bce_elem(x.y, t.y), s);
        s = fmaf(wv.z, bce_elem(x.z, t.z), s);
        s = fmaf(wv.w, bce_elem(x.w, t.w), s);
        acc += s;
    }

    // Intra-block reduce
    #pragma unroll
    for (int o = 16; o > 0; o >>= 1)
        acc += __shfl_xor_sync(0xffffffffu, acc, o);
    if ((tid & 31) == 0) wred[tid >> 5] = acc;
    __syncthreads();

    if (tid == 0) {
        float a = 0.0f;
        #pragma unroll
        for (int i = 0; i < NTHREADS / 32; ++i) a += wred[i];
        g_partials[blockIdx.x] = a;
        __threadfence();
        unsigned old = atomicAdd(&g_done, 1u);
        s_last = (old == NBLOCKS - 1);
    }
    __syncthreads();

    // Last block performs the fixed-order final reduction (deterministic).
    if (s_last) {
        __shared__ float fin[NTHREADS];
        float a = 0.0f;
        for (int i = tid; i < NBLOCKS; i += NTHREADS)   // fixed order
            a += g_partials[i];
        fin[tid] = a;
        __syncthreads();
        #pragma unroll
        for (int o = NTHREADS / 2; o > 0; o >>= 1) {
            if (tid < o) fin[tid] += fin[tid + o];
            __syncthreads();
        }
        if (tid == 0) {
            out[0] = fin[0];
            g_done = 0;                 // re-arm for next graph replay
        }
    }
}

extern "C" void kernel_launch(void* const* d_in, const int* in_sizes, int n_in,
                              void* d_out, int out_size) {
    (void)in_sizes; (void)n_in; (void)out_size;
    loss_fused<<<NBLOCKS, NTHREADS>>>(
        (const float4*)d_in[0], (const float4*)d_in[1],
        (const float*)d_in[2],  (const float*)d_in[3],
        (float*)d_out);
}